// round 4
// baseline (speedup 1.0000x reference)
#include <cuda_runtime.h>
#include <math.h>

// Fixed problem shapes
#define NN 100000
#define DD 256
#define EE 200000
#define BB 50000
#define WDECAY 1e-6f
#define ROW4 (DD / 4)   // 64 float4 per row
#define CAP 48          // max incident edges per node (Poisson(4); P(>48) ~ 0)

// Scratch (device globals — no runtime allocation allowed)
__device__ float g_feat[(size_t)BB * 64];
__device__ float g_next_time;
__device__ float g_decay;
__device__ int   g_deg[NN];
__device__ int2  g_adj[(size_t)NN * CAP];   // {opp_node, float_bits(tw)}

__device__ __forceinline__ float4 f4s(float4 a, float s) {
    return make_float4(a.x * s, a.y * s, a.z * s, a.w * s);
}

// Packed f32x2 helpers (Blackwell 2x fp32 rate; FFMA2 only reachable via PTX)
#define FMAX2(d, a, b, c) \
    asm("fma.rn.f32x2 %0, %1, %2, %3;" : "=l"(d) : "l"(a), "l"(b), "l"(c))
#define PACKF(d, lo, hi) \
    asm("mov.b64 %0, {%1, %2};" : "=l"(d) : "f"(lo), "f"(hi))
#define UNPACKF(lo, hi, d) \
    asm("mov.b64 {%0, %1}, %2;" : "=f"(lo), "=f"(hi) : "l"(d))

// ---------------------------------------------------------------------------
// Kernel 0: scalars
// ---------------------------------------------------------------------------
__global__ void k_scalars(const float* __restrict__ times,
                          const float* __restrict__ now_time, int E) {
    float nt = times[E - 1];
    g_next_time = nt;
    g_decay = expf(-WDECAY * (nt - now_time[0]));
}

// ---------------------------------------------------------------------------
// Zero degrees
// ---------------------------------------------------------------------------
__global__ void k_zero(int N) {
    int i = blockIdx.x * blockDim.x + threadIdx.x;
    if (i < N) g_deg[i] = 0;
}

// ---------------------------------------------------------------------------
// Build padded adjacency in one pass (no scan)
// ---------------------------------------------------------------------------
__global__ void k_build(const int* __restrict__ src,
                        const int* __restrict__ dst,
                        const float* __restrict__ times, int E) {
    int e = blockIdx.x * blockDim.x + threadIdx.x;
    if (e >= E) return;
    int s = src[e];
    int t = dst[e];
    float w = expf(-WDECAY * (g_next_time - times[e]));
    int wb = __float_as_int(w);
    int p1 = atomicAdd(&g_deg[s], 1);
    if (p1 < CAP) g_adj[(size_t)s * CAP + p1] = make_int2(t, wb);
    int p2 = atomicAdd(&g_deg[t], 1);
    if (p2 < CAP) g_adj[(size_t)t * CAP + p2] = make_int2(s, wb);
}

// ---------------------------------------------------------------------------
// Fused pair kernel (unchanged from R3): compute the 8 updated rows for (s,t)
// on the fly, Gram + log1p -> g_feat. One 64-thread block per pair.
// ---------------------------------------------------------------------------
__device__ const int TRI_I[36] = {0,0,0,0,0,0,0,0, 1,1,1,1,1,1,1, 2,2,2,2,2,2,
                                  3,3,3,3,3, 4,4,4,4, 5,5,5, 6,6, 7};
__device__ const int TRI_J[36] = {0,1,2,3,4,5,6,7, 1,2,3,4,5,6,7, 2,3,4,5,6,7,
                                  3,4,5,6,7, 4,5,6,7, 5,6,7, 6,7, 7};

__global__ void __launch_bounds__(64) k_pair(
    const float* __restrict__ rp0, const float* __restrict__ rp1,
    const float* __restrict__ rp2, const float* __restrict__ rp3,
    const int* __restrict__ qs, const int* __restrict__ qd, int B) {
    int pair = blockIdx.x;
    if (pair >= B) return;
    int tid = threadIdx.x;           // 0..63 (column slice)
    int lane = tid & 31, wid = tid >> 5;

    __shared__ float sh_part[2][36];
    __shared__ float sh_feat[64];

    int s = qs[pair];
    int t = qd[pair];
    float d = g_decay;
    float d2 = d * d;
    float d3 = d2 * d;

    const float4* r0 = (const float4*)rp0;
    const float4* r1 = (const float4*)rp1;
    const float4* r2 = (const float4*)rp2;
    const float4* r3 = (const float4*)rp3;

    size_t so = (size_t)s * ROW4 + tid;
    size_t to = (size_t)t * ROW4 + tid;

    float4 acc[8];
    acc[0] = __ldg(r0 + so);
    acc[1] = f4s(__ldg(r1 + so), d);
    acc[2] = f4s(__ldg(r2 + so), d2);
    acc[3] = f4s(__ldg(r3 + so), d3);
    acc[4] = __ldg(r0 + to);
    acc[5] = f4s(__ldg(r1 + to), d);
    acc[6] = f4s(__ldg(r2 + to), d2);
    acc[7] = f4s(__ldg(r3 + to), d3);

#pragma unroll
    for (int side = 0; side < 2; side++) {
        int v = side ? t : s;
        int base = side * 4;
        int g = min(__ldg(&g_deg[v]), CAP);
        const int2* adj = g_adj + (size_t)v * CAP;
        int2 a_next;
        if (g > 0) a_next = __ldg(adj);
        for (int j = 0; j < g; j++) {
            int2 a = a_next;
            if (j + 1 < g) a_next = __ldg(adj + j + 1);
            int u = a.x;
            float w = __int_as_float(a.y);
            size_t uo = (size_t)u * ROW4 + tid;
            float4 x0 = __ldg(r0 + uo);
            float4 x1 = __ldg(r1 + uo);
            float4 x2 = __ldg(r2 + uo);
            float w1c = w;
            float w2c = w * d;
            float w3c = w * d2;
            acc[base + 1].x += w1c * x0.x; acc[base + 1].y += w1c * x0.y;
            acc[base + 1].z += w1c * x0.z; acc[base + 1].w += w1c * x0.w;
            acc[base + 2].x += w2c * x1.x; acc[base + 2].y += w2c * x1.y;
            acc[base + 2].z += w2c * x1.z; acc[base + 2].w += w2c * x1.w;
            acc[base + 3].x += w3c * x2.x; acc[base + 3].y += w3c * x2.y;
            acc[base + 3].z += w3c * x2.z; acc[base + 3].w += w3c * x2.w;
        }
    }

#pragma unroll
    for (int i = 0; i < 8; i++) {
#pragma unroll
        for (int j = i; j < 8; j++) {
            const int idx = i * 8 - (i * (i - 1)) / 2 + (j - i);
            float p = acc[i].x * acc[j].x + acc[i].y * acc[j].y +
                      acc[i].z * acc[j].z + acc[i].w * acc[j].w;
            p += __shfl_xor_sync(0xFFFFFFFF, p, 16);
            p += __shfl_xor_sync(0xFFFFFFFF, p, 8);
            p += __shfl_xor_sync(0xFFFFFFFF, p, 4);
            p += __shfl_xor_sync(0xFFFFFFFF, p, 2);
            p += __shfl_xor_sync(0xFFFFFFFF, p, 1);
            if (lane == 0) sh_part[wid][idx] = p;
        }
    }
    __syncthreads();
    if (tid < 36) {
        float v = sh_part[0][tid] + sh_part[1][tid];
        v = log1pf(fmaxf(v, 0.0f));
        int i = TRI_I[tid], j = TRI_J[tid];
        sh_feat[i * 8 + j] = v;
        sh_feat[j * 8 + i] = v;
    }
    __syncthreads();
    g_feat[(size_t)pair * 64 + tid] = sh_feat[tid];
}

// ---------------------------------------------------------------------------
// MLP with packed f32x2 math.
// Tile = 32 pairs, 256 threads.
// Shared layout (floats):
//   [0, 9216)        sH : h transposed, hT[jj][i], pitch 36 (16B-aligned quads)
//   [9216, 25600)    region B: sF (feat tile, 2048 floats) during phase 1,
//                    then overlaid by sW2 (w2 staged, 16384 floats) in phase 2.
// Phase 1: h[i][j] = relu(b1[j] + sum_f feat[i][f] w1[f][j]); pack across f.
// Phase 2: out[i][o] = b2[o] + sum_jj h[i][jj] w2[jj][o];      pack across i.
// ---------------------------------------------------------------------------
#define SH_PITCH 36
#define SMEM_MLP_FLOATS (9216 + 16384)

__global__ void __launch_bounds__(256, 2) k_mlp(
    const float* __restrict__ w1, const float* __restrict__ b1,
    const float* __restrict__ w2, const float* __restrict__ b2,
    float* __restrict__ out, int B) {
    extern __shared__ float smem[];
    float* sH = smem;                 // 9216 floats
    float* sF = smem + 9216;          // 2048 floats (phase 1)
    float* sW2 = smem + 9216;         // 16384 floats (phase 2, overlays sF)

    int base = blockIdx.x * 32;
    int j = threadIdx.x;              // 0..255 = hidden column

    // load feat tile (zero-pad past B)
    for (int idx = j; idx < 32 * 64; idx += 256) {
        long gi = (long)base * 64 + idx;
        sF[idx] = (gi < (long)B * 64) ? g_feat[gi] : 0.0f;
    }
    __syncthreads();

    // ---- phase 1 ----
    unsigned long long w1p[32];
#pragma unroll
    for (int k = 0; k < 32; k++) {
        float a = __ldg(w1 + (2 * k) * 256 + j);
        float b = __ldg(w1 + (2 * k + 1) * 256 + j);
        PACKF(w1p[k], a, b);
    }
    float b1j = __ldg(b1 + j);
    const ulonglong2* sU = (const ulonglong2*)sF;

#pragma unroll 4
    for (int i = 0; i < 32; i++) {
        unsigned long long a0 = 0ULL, a1 = 0ULL;
#pragma unroll
        for (int f4 = 0; f4 < 16; f4++) {
            ulonglong2 u = sU[i * 16 + f4];
            FMAX2(a0, u.x, w1p[2 * f4], a0);
            FMAX2(a1, u.y, w1p[2 * f4 + 1], a1);
        }
        float l0, h0, l1, h1;
        UNPACKF(l0, h0, a0);
        UNPACKF(l1, h1, a1);
        float h = fmaxf(l0 + h0 + l1 + h1 + b1j, 0.0f);
        sH[j * SH_PITCH + i] = h;     // hT[jj=j][i]
    }
    __syncthreads();

    // ---- stage w2 (overlays sF) ----
    for (int idx = threadIdx.x; idx < 4096; idx += 256)
        ((float4*)sW2)[idx] = __ldg((const float4*)w2 + idx);
    __syncthreads();

    // ---- phase 2 ----
    int o = threadIdx.x & 63;
    int g = threadIdx.x >> 6;         // i-group: rows g*8 .. g*8+7
    unsigned long long acc[4] = {0ULL, 0ULL, 0ULL, 0ULL};

#pragma unroll 4
    for (int jj = 0; jj < 256; jj++) {
        float w = sW2[jj * 64 + o];
        unsigned long long wp;
        PACKF(wp, w, w);
        const ulonglong2* hp = (const ulonglong2*)(sH + jj * SH_PITCH + g * 8);
        ulonglong2 x = hp[0];
        ulonglong2 y = hp[1];
        FMAX2(acc[0], x.x, wp, acc[0]);
        FMAX2(acc[1], x.y, wp, acc[1]);
        FMAX2(acc[2], y.x, wp, acc[2]);
        FMAX2(acc[3], y.y, wp, acc[3]);
    }

    float b2o = __ldg(b2 + o);
#pragma unroll
    for (int m = 0; m < 4; m++) {
        float lo, hi;
        UNPACKF(lo, hi, acc[m]);
        int i = g * 8 + 2 * m;
        if (base + i < B)     out[(size_t)(base + i) * 64 + o]     = lo + b2o;
        if (base + i + 1 < B) out[(size_t)(base + i + 1) * 64 + o] = hi + b2o;
    }
}

// ---------------------------------------------------------------------------
extern "C" void kernel_launch(void* const* d_in, const int* in_sizes, int n_in,
                              void* d_out, int out_size) {
    const float* rp0      = (const float*)d_in[0];
    const float* rp1      = (const float*)d_in[1];
    const float* rp2      = (const float*)d_in[2];
    const float* rp3      = (const float*)d_in[3];
    const float* times    = (const float*)d_in[4];
    const float* now_time = (const float*)d_in[5];
    const float* w1       = (const float*)d_in[6];
    const float* b1       = (const float*)d_in[7];
    const float* w2       = (const float*)d_in[8];
    const float* b2       = (const float*)d_in[9];
    const int*   src      = (const int*)d_in[10];
    const int*   dst      = (const int*)d_in[11];
    const int*   qs       = (const int*)d_in[12];
    const int*   qd       = (const int*)d_in[13];

    int E = in_sizes[4];
    int B = in_sizes[12];
    int N = in_sizes[1] / DD;

    static int smem_set = 0;
    if (!smem_set) {
        cudaFuncSetAttribute(k_mlp, cudaFuncAttributeMaxDynamicSharedMemorySize,
                             SMEM_MLP_FLOATS * 4);
        smem_set = 1;
    }

    k_scalars<<<1, 1>>>(times, now_time, E);
    k_zero<<<(N + 255) / 256, 256>>>(N);
    k_build<<<(E + 255) / 256, 256>>>(src, dst, times, E);
    k_pair<<<B, 64>>>(rp0, rp1, rp2, rp3, qs, qd, B);
    k_mlp<<<(B + 31) / 32, 256, SMEM_MLP_FLOATS * 4>>>(w1, b1, w2, b2,
                                                       (float*)d_out, B);
}

// round 5
// speedup vs baseline: 1.0837x; 1.0837x over previous
#include <cuda_runtime.h>
#include <math.h>

// Fixed problem shapes
#define NN 100000
#define DD 256
#define EE 200000
#define BB 50000
#define WDECAY 1e-6f
#define ROW2 (DD / 2)   // 128 float2 per row
#define CAP 48          // max incident edges per node (Poisson(4); P(>48) ~ 0)

// Scratch (device globals — no runtime allocation allowed)
__device__ float g_feat[(size_t)BB * 64];
__device__ float g_next_time;
__device__ float g_decay;
__device__ int   g_deg[NN];
__device__ int2  g_adj[(size_t)NN * CAP];   // {opp_node, float_bits(tw)}

// ---------------------------------------------------------------------------
// Kernel 0: scalars
// ---------------------------------------------------------------------------
__global__ void k_scalars(const float* __restrict__ times,
                          const float* __restrict__ now_time, int E) {
    float nt = times[E - 1];
    g_next_time = nt;
    g_decay = expf(-WDECAY * (nt - now_time[0]));
}

// ---------------------------------------------------------------------------
// Zero degrees
// ---------------------------------------------------------------------------
__global__ void k_zero(int N) {
    int i = blockIdx.x * blockDim.x + threadIdx.x;
    if (i < N) g_deg[i] = 0;
}

// ---------------------------------------------------------------------------
// Build padded adjacency in one pass (no scan)
// ---------------------------------------------------------------------------
__global__ void k_build(const int* __restrict__ src,
                        const int* __restrict__ dst,
                        const float* __restrict__ times, int E) {
    int e = blockIdx.x * blockDim.x + threadIdx.x;
    if (e >= E) return;
    int s = src[e];
    int t = dst[e];
    float w = expf(-WDECAY * (g_next_time - times[e]));
    int wb = __float_as_int(w);
    int p1 = atomicAdd(&g_deg[s], 1);
    if (p1 < CAP) g_adj[(size_t)s * CAP + p1] = make_int2(t, wb);
    int p2 = atomicAdd(&g_deg[t], 1);
    if (p2 < CAP) g_adj[(size_t)t * CAP + p2] = make_int2(s, wb);
}

// ---------------------------------------------------------------------------
// Fused pair kernel: 128 threads/pair, float2 column slices (16 acc regs ->
// higher occupancy / more loads in flight than the float4/64-thread version).
// Computes the 8 updated rows for (s,t) on the fly, Gram + log1p -> g_feat.
// ---------------------------------------------------------------------------
__device__ const int TRI_I[36] = {0,0,0,0,0,0,0,0, 1,1,1,1,1,1,1, 2,2,2,2,2,2,
                                  3,3,3,3,3, 4,4,4,4, 5,5,5, 6,6, 7};
__device__ const int TRI_J[36] = {0,1,2,3,4,5,6,7, 1,2,3,4,5,6,7, 2,3,4,5,6,7,
                                  3,4,5,6,7, 4,5,6,7, 5,6,7, 6,7, 7};

__global__ void __launch_bounds__(128) k_pair(
    const float* __restrict__ rp0, const float* __restrict__ rp1,
    const float* __restrict__ rp2, const float* __restrict__ rp3,
    const int* __restrict__ qs, const int* __restrict__ qd, int B) {
    int pair = blockIdx.x;
    if (pair >= B) return;
    int tid = threadIdx.x;           // 0..127 (float2 column slice)
    int lane = tid & 31, wid = tid >> 5;

    __shared__ float sh_part[4][36];
    __shared__ float sh_feat[64];

    int s = qs[pair];
    int t = qd[pair];
    float d = g_decay;
    float d2 = d * d;
    float d3 = d2 * d;

    const float2* r0 = (const float2*)rp0;
    const float2* r1 = (const float2*)rp1;
    const float2* r2 = (const float2*)rp2;
    const float2* r3 = (const float2*)rp3;

    size_t so = (size_t)s * ROW2 + tid;
    size_t to = (size_t)t * ROW2 + tid;

    float2 acc[8];
    {
        float2 v;
        acc[0] = __ldg(r0 + so);
        v = __ldg(r1 + so); acc[1] = make_float2(v.x * d,  v.y * d);
        v = __ldg(r2 + so); acc[2] = make_float2(v.x * d2, v.y * d2);
        v = __ldg(r3 + so); acc[3] = make_float2(v.x * d3, v.y * d3);
        acc[4] = __ldg(r0 + to);
        v = __ldg(r1 + to); acc[5] = make_float2(v.x * d,  v.y * d);
        v = __ldg(r2 + to); acc[6] = make_float2(v.x * d2, v.y * d2);
        v = __ldg(r3 + to); acc[7] = make_float2(v.x * d3, v.y * d3);
    }

    // accumulate incident-edge contributions for both endpoints
#pragma unroll
    for (int side = 0; side < 2; side++) {
        int v = side ? t : s;
        int base = side * 4;
        int g = min(__ldg(&g_deg[v]), CAP);
        const int2* adj = g_adj + (size_t)v * CAP;
        int2 a_next;
        if (g > 0) a_next = __ldg(adj);
        for (int j = 0; j < g; j++) {
            int2 a = a_next;
            if (j + 1 < g) a_next = __ldg(adj + j + 1);
            int u = a.x;
            float w = __int_as_float(a.y);
            size_t uo = (size_t)u * ROW2 + tid;
            float2 x0 = __ldg(r0 + uo);
            float2 x1 = __ldg(r1 + uo);
            float2 x2 = __ldg(r2 + uo);
            float w1c = w;
            float w2c = w * d;
            float w3c = w * d2;
            acc[base + 1].x += w1c * x0.x; acc[base + 1].y += w1c * x0.y;
            acc[base + 2].x += w2c * x1.x; acc[base + 2].y += w2c * x1.y;
            acc[base + 3].x += w3c * x2.x; acc[base + 3].y += w3c * x2.y;
        }
    }

    // Gram: 36 unique dot products over the 8 rows
#pragma unroll
    for (int i = 0; i < 8; i++) {
#pragma unroll
        for (int j = i; j < 8; j++) {
            const int idx = i * 8 - (i * (i - 1)) / 2 + (j - i);
            float p = acc[i].x * acc[j].x + acc[i].y * acc[j].y;
            p += __shfl_xor_sync(0xFFFFFFFF, p, 16);
            p += __shfl_xor_sync(0xFFFFFFFF, p, 8);
            p += __shfl_xor_sync(0xFFFFFFFF, p, 4);
            p += __shfl_xor_sync(0xFFFFFFFF, p, 2);
            p += __shfl_xor_sync(0xFFFFFFFF, p, 1);
            if (lane == 0) sh_part[wid][idx] = p;
        }
    }
    __syncthreads();
    if (tid < 36) {
        float v = sh_part[0][tid] + sh_part[1][tid] +
                  sh_part[2][tid] + sh_part[3][tid];
        v = log1pf(fmaxf(v, 0.0f));
        int i = TRI_I[tid], j = TRI_J[tid];
        sh_feat[i * 8 + j] = v;
        sh_feat[j * 8 + i] = v;
    }
    __syncthreads();
    if (tid < 64) g_feat[(size_t)pair * 64 + tid] = sh_feat[tid];
}

// ---------------------------------------------------------------------------
// MLP: out = relu(feat @ w1 + b1) @ w2 + b2   (R3 version — known good)
// ---------------------------------------------------------------------------
__global__ void k_mlp(const float* __restrict__ w1, const float* __restrict__ b1,
                      const float* __restrict__ w2, const float* __restrict__ b2,
                      float* __restrict__ out, int B) {
    __shared__ float sF[32 * 64];
    __shared__ float sH[32 * 256];
    int base = blockIdx.x * 32;

    for (int i = threadIdx.x; i < 32 * 64; i += 256) {
        size_t gi = (size_t)base * 64 + i;
        sF[i] = (base * 64 + i < B * 64) ? g_feat[gi] : 0.0f;
    }
    __syncthreads();

    int j = threadIdx.x;
    float w1col[64];
#pragma unroll
    for (int f = 0; f < 64; f++) w1col[f] = __ldg(w1 + f * 256 + j);
    float bj = __ldg(b1 + j);
#pragma unroll 4
    for (int i = 0; i < 32; i++) {
        float acc = bj;
#pragma unroll
        for (int f = 0; f < 64; f++) acc += sF[i * 64 + f] * w1col[f];
        sH[i * 256 + j] = fmaxf(acc, 0.0f);
    }
    __syncthreads();

    int o = threadIdx.x & 63;
    int i0 = threadIdx.x >> 6;
    float acc[8];
    float b2o = __ldg(b2 + o);
#pragma unroll
    for (int k = 0; k < 8; k++) acc[k] = b2o;
    for (int jj = 0; jj < 256; jj++) {
        float wv = __ldg(w2 + jj * 64 + o);
#pragma unroll
        for (int k = 0; k < 8; k++) acc[k] += sH[(i0 + k * 4) * 256 + jj] * wv;
    }
#pragma unroll
    for (int k = 0; k < 8; k++) {
        int i = i0 + k * 4;
        if (base + i < B) out[(size_t)(base + i) * 64 + o] = acc[k];
    }
}

// ---------------------------------------------------------------------------
extern "C" void kernel_launch(void* const* d_in, const int* in_sizes, int n_in,
                              void* d_out, int out_size) {
    const float* rp0      = (const float*)d_in[0];
    const float* rp1      = (const float*)d_in[1];
    const float* rp2      = (const float*)d_in[2];
    const float* rp3      = (const float*)d_in[3];
    const float* times    = (const float*)d_in[4];
    const float* now_time = (const float*)d_in[5];
    const float* w1       = (const float*)d_in[6];
    const float* b1       = (const float*)d_in[7];
    const float* w2       = (const float*)d_in[8];
    const float* b2       = (const float*)d_in[9];
    const int*   src      = (const int*)d_in[10];
    const int*   dst      = (const int*)d_in[11];
    const int*   qs       = (const int*)d_in[12];
    const int*   qd       = (const int*)d_in[13];

    int E = in_sizes[4];
    int B = in_sizes[12];
    int N = in_sizes[1] / DD;

    k_scalars<<<1, 1>>>(times, now_time, E);
    k_zero<<<(N + 255) / 256, 256>>>(N);
    k_build<<<(E + 255) / 256, 256>>>(src, dst, times, E);
    k_pair<<<B, 128>>>(rp0, rp1, rp2, rp3, qs, qd, B);
    k_mlp<<<(B + 31) / 32, 256>>>(w1, b1, w2, b2, (float*)d_out, B);
}

// round 6
// speedup vs baseline: 1.6054x; 1.4814x over previous
#include <cuda_runtime.h>
#include <math.h>

// Fixed problem shapes
#define NN 100000
#define DD 256
#define EE 200000
#define BB 50000
#define WDECAY 1e-6f
#define ROW4 (DD / 4)   // 64 float4 per row
#define CAP 48          // max incident edges per node (Poisson(4); P(>48) ~ 0)

// Scratch (device globals — no runtime allocation allowed)
__device__ float g_feat[(size_t)BB * 64];
__device__ float g_next_time;
__device__ float g_decay;
__device__ int   g_deg[NN];
__device__ int2  g_adj[(size_t)NN * CAP];   // {opp_node, float_bits(tw)}

__device__ __forceinline__ float4 f4s(float4 a, float s) {
    return make_float4(a.x * s, a.y * s, a.z * s, a.w * s);
}

__device__ __forceinline__ unsigned f2tf32(float x) {
    unsigned r;
    asm("cvt.rna.tf32.f32 %0, %1;" : "=r"(r) : "f"(x));
    return r;
}

#define MMA_TF32(d0, d1, d2, d3, a0, a1, a2, a3, b0, b1)                     \
    asm("mma.sync.aligned.m16n8k8.row.col.f32.tf32.tf32.f32 "                \
        "{%0,%1,%2,%3}, {%4,%5,%6,%7}, {%8,%9}, {%0,%1,%2,%3};"              \
        : "+f"(d0), "+f"(d1), "+f"(d2), "+f"(d3)                             \
        : "r"(a0), "r"(a1), "r"(a2), "r"(a3), "r"(b0), "r"(b1))

// ---------------------------------------------------------------------------
// Kernel 0: scalars
// ---------------------------------------------------------------------------
__global__ void k_scalars(const float* __restrict__ times,
                          const float* __restrict__ now_time, int E) {
    float nt = times[E - 1];
    g_next_time = nt;
    g_decay = expf(-WDECAY * (nt - now_time[0]));
}

// ---------------------------------------------------------------------------
// Zero degrees
// ---------------------------------------------------------------------------
__global__ void k_zero(int N) {
    int i = blockIdx.x * blockDim.x + threadIdx.x;
    if (i < N) g_deg[i] = 0;
}

// ---------------------------------------------------------------------------
// Build padded adjacency in one pass (no scan)
// ---------------------------------------------------------------------------
__global__ void k_build(const int* __restrict__ src,
                        const int* __restrict__ dst,
                        const float* __restrict__ times, int E) {
    int e = blockIdx.x * blockDim.x + threadIdx.x;
    if (e >= E) return;
    int s = src[e];
    int t = dst[e];
    float w = expf(-WDECAY * (g_next_time - times[e]));
    int wb = __float_as_int(w);
    int p1 = atomicAdd(&g_deg[s], 1);
    if (p1 < CAP) g_adj[(size_t)s * CAP + p1] = make_int2(t, wb);
    int p2 = atomicAdd(&g_deg[t], 1);
    if (p2 < CAP) g_adj[(size_t)t * CAP + p2] = make_int2(s, wb);
}

// ---------------------------------------------------------------------------
// Fused pair kernel (R3 version — best measured): 64 threads/pair, float4
// column slices. Computes the 8 updated rows for (s,t) on the fly,
// Gram + log1p -> g_feat.
// ---------------------------------------------------------------------------
__device__ const int TRI_I[36] = {0,0,0,0,0,0,0,0, 1,1,1,1,1,1,1, 2,2,2,2,2,2,
                                  3,3,3,3,3, 4,4,4,4, 5,5,5, 6,6, 7};
__device__ const int TRI_J[36] = {0,1,2,3,4,5,6,7, 1,2,3,4,5,6,7, 2,3,4,5,6,7,
                                  3,4,5,6,7, 4,5,6,7, 5,6,7, 6,7, 7};

__global__ void __launch_bounds__(64) k_pair(
    const float* __restrict__ rp0, const float* __restrict__ rp1,
    const float* __restrict__ rp2, const float* __restrict__ rp3,
    const int* __restrict__ qs, const int* __restrict__ qd, int B) {
    int pair = blockIdx.x;
    if (pair >= B) return;
    int tid = threadIdx.x;           // 0..63 (column slice)
    int lane = tid & 31, wid = tid >> 5;

    __shared__ float sh_part[2][36];
    __shared__ float sh_feat[64];

    int s = qs[pair];
    int t = qd[pair];
    float d = g_decay;
    float d2 = d * d;
    float d3 = d2 * d;

    const float4* r0 = (const float4*)rp0;
    const float4* r1 = (const float4*)rp1;
    const float4* r2 = (const float4*)rp2;
    const float4* r3 = (const float4*)rp3;

    size_t so = (size_t)s * ROW4 + tid;
    size_t to = (size_t)t * ROW4 + tid;

    float4 acc[8];
    acc[0] = __ldg(r0 + so);
    acc[1] = f4s(__ldg(r1 + so), d);
    acc[2] = f4s(__ldg(r2 + so), d2);
    acc[3] = f4s(__ldg(r3 + so), d3);
    acc[4] = __ldg(r0 + to);
    acc[5] = f4s(__ldg(r1 + to), d);
    acc[6] = f4s(__ldg(r2 + to), d2);
    acc[7] = f4s(__ldg(r3 + to), d3);

#pragma unroll
    for (int side = 0; side < 2; side++) {
        int v = side ? t : s;
        int base = side * 4;
        int g = min(__ldg(&g_deg[v]), CAP);
        const int2* adj = g_adj + (size_t)v * CAP;
        int2 a_next;
        if (g > 0) a_next = __ldg(adj);
        for (int j = 0; j < g; j++) {
            int2 a = a_next;
            if (j + 1 < g) a_next = __ldg(adj + j + 1);
            int u = a.x;
            float w = __int_as_float(a.y);
            size_t uo = (size_t)u * ROW4 + tid;
            float4 x0 = __ldg(r0 + uo);
            float4 x1 = __ldg(r1 + uo);
            float4 x2 = __ldg(r2 + uo);
            float w1c = w;
            float w2c = w * d;
            float w3c = w * d2;
            acc[base + 1].x += w1c * x0.x; acc[base + 1].y += w1c * x0.y;
            acc[base + 1].z += w1c * x0.z; acc[base + 1].w += w1c * x0.w;
            acc[base + 2].x += w2c * x1.x; acc[base + 2].y += w2c * x1.y;
            acc[base + 2].z += w2c * x1.z; acc[base + 2].w += w2c * x1.w;
            acc[base + 3].x += w3c * x2.x; acc[base + 3].y += w3c * x2.y;
            acc[base + 3].z += w3c * x2.z; acc[base + 3].w += w3c * x2.w;
        }
    }

#pragma unroll
    for (int i = 0; i < 8; i++) {
#pragma unroll
        for (int j = i; j < 8; j++) {
            const int idx = i * 8 - (i * (i - 1)) / 2 + (j - i);
            float p = acc[i].x * acc[j].x + acc[i].y * acc[j].y +
                      acc[i].z * acc[j].z + acc[i].w * acc[j].w;
            p += __shfl_xor_sync(0xFFFFFFFF, p, 16);
            p += __shfl_xor_sync(0xFFFFFFFF, p, 8);
            p += __shfl_xor_sync(0xFFFFFFFF, p, 4);
            p += __shfl_xor_sync(0xFFFFFFFF, p, 2);
            p += __shfl_xor_sync(0xFFFFFFFF, p, 1);
            if (lane == 0) sh_part[wid][idx] = p;
        }
    }
    __syncthreads();
    if (tid < 36) {
        float v = sh_part[0][tid] + sh_part[1][tid];
        v = log1pf(fmaxf(v, 0.0f));
        int i = TRI_I[tid], j = TRI_J[tid];
        sh_feat[i * 8 + j] = v;
        sh_feat[j * 8 + i] = v;
    }
    __syncthreads();
    g_feat[(size_t)pair * 64 + tid] = sh_feat[tid];
}

// ---------------------------------------------------------------------------
// MLP via tf32 mma.sync (tensor cores).
// 128 pairs/block, 8 warps; warp w owns rows 16w..16w+15 privately.
// Hidden dim processed in 4 chunks of 64:
//   GEMM1 chunk: h = relu(feat @ w1[:,chunk] + b1[chunk]) -> sR (warp-private)
//   GEMM2 chunk: out += h @ w2[chunk,:]
// Shared layout (floats), pitches chosen so pitch % 32 == 8 (B frags) or == 4
// (A frags) => conflict-free LDS:
//   sW1: [64][264]   tf32 bits of w1
//   sW2: [256][72]   tf32 bits of w2
//   sF : [128][68]   tf32 bits of feat tile
//   sR : [128][68]   tf32 bits of relu chunk
// ---------------------------------------------------------------------------
#define P_W1 264
#define P_W2 72
#define P_F  68
#define SM_W1 (64 * P_W1)
#define SM_W2 (256 * P_W2)
#define SM_F  (128 * P_F)
#define SMEM_MLP (SM_W1 + SM_W2 + 2 * SM_F)   // floats

__global__ void __launch_bounds__(256, 1) k_mlp(
    const float* __restrict__ w1, const float* __restrict__ b1,
    const float* __restrict__ w2, const float* __restrict__ b2,
    float* __restrict__ out, int B) {
    extern __shared__ unsigned smu[];
    unsigned* sW1 = smu;
    unsigned* sW2 = smu + SM_W1;
    unsigned* sF  = smu + SM_W1 + SM_W2;
    unsigned* sR  = smu + SM_W1 + SM_W2 + SM_F;

    int base = blockIdx.x * 128;
    int tid = threadIdx.x;
    int lane = tid & 31;
    int warp = tid >> 5;              // 0..7
    int gq = lane >> 2;               // groupID 0..7
    int tq = lane & 3;                // thread-in-group 0..3
    int m0 = warp * 16;

    // ---- stage weights + feat (tf32-converted) ----
    for (int i = tid; i < 64 * 64; i += 256) {        // w1: 64x256 via f4
        float4 v = __ldg((const float4*)w1 + i);
        int r = i >> 6, c = (i & 63) << 2;
        unsigned* p = sW1 + r * P_W1 + c;
        p[0] = f2tf32(v.x); p[1] = f2tf32(v.y);
        p[2] = f2tf32(v.z); p[3] = f2tf32(v.w);
    }
    for (int i = tid; i < 256 * 16; i += 256) {       // w2: 256x64 via f4
        float4 v = __ldg((const float4*)w2 + i);
        int r = i >> 4, c = (i & 15) << 2;
        unsigned* p = sW2 + r * P_W2 + c;
        p[0] = f2tf32(v.x); p[1] = f2tf32(v.y);
        p[2] = f2tf32(v.z); p[3] = f2tf32(v.w);
    }
    for (int i = tid; i < 128 * 16; i += 256) {       // feat: 128x64 via f4
        int r = i >> 4, c = (i & 15) << 2;
        float4 v = make_float4(0.f, 0.f, 0.f, 0.f);
        if (base + r < B) v = __ldg((const float4*)g_feat + (size_t)(base + r) * 16 + (i & 15));
        unsigned* p = sF + r * P_F + c;
        p[0] = f2tf32(v.x); p[1] = f2tf32(v.y);
        p[2] = f2tf32(v.z); p[3] = f2tf32(v.w);
    }
    __syncthreads();

    // ---- hoist GEMM1 A fragments (feat rows m0..m0+15, K=64) ----
    unsigned aF[8][4];
#pragma unroll
    for (int k8 = 0; k8 < 8; k8++) {
        aF[k8][0] = sF[(m0 + gq) * P_F + k8 * 8 + tq];
        aF[k8][1] = sF[(m0 + gq + 8) * P_F + k8 * 8 + tq];
        aF[k8][2] = sF[(m0 + gq) * P_F + k8 * 8 + tq + 4];
        aF[k8][3] = sF[(m0 + gq + 8) * P_F + k8 * 8 + tq + 4];
    }

    // persistent output accumulators: 8 n-subtiles x 4
    float o0[8], o1[8], o2[8], o3[8];
#pragma unroll
    for (int n8 = 0; n8 < 8; n8++) { o0[n8] = o1[n8] = o2[n8] = o3[n8] = 0.f; }

    for (int c = 0; c < 4; c++) {
        int cc = c * 64;
        // GEMM1 chunk + relu -> sR (warp-private rows)
#pragma unroll
        for (int n8 = 0; n8 < 8; n8++) {
            float d0 = 0.f, d1 = 0.f, d2 = 0.f, d3 = 0.f;
#pragma unroll
            for (int k8 = 0; k8 < 8; k8++) {
                unsigned b0 = sW1[(k8 * 8 + tq) * P_W1 + cc + n8 * 8 + gq];
                unsigned b1r = sW1[(k8 * 8 + tq + 4) * P_W1 + cc + n8 * 8 + gq];
                MMA_TF32(d0, d1, d2, d3,
                         aF[k8][0], aF[k8][1], aF[k8][2], aF[k8][3], b0, b1r);
            }
            float bb0 = __ldg(b1 + cc + n8 * 8 + 2 * tq);
            float bb1 = __ldg(b1 + cc + n8 * 8 + 2 * tq + 1);
            d0 = fmaxf(d0 + bb0, 0.f);
            d1 = fmaxf(d1 + bb1, 0.f);
            d2 = fmaxf(d2 + bb0, 0.f);
            d3 = fmaxf(d3 + bb1, 0.f);
            unsigned* p = sR + (m0 + gq) * P_F + n8 * 8 + 2 * tq;
            p[0] = f2tf32(d0); p[1] = f2tf32(d1);
            p = sR + (m0 + gq + 8) * P_F + n8 * 8 + 2 * tq;
            p[0] = f2tf32(d2); p[1] = f2tf32(d3);
        }
        __syncwarp();

        // GEMM2 chunk: out += relu_chunk @ w2[chunk]
        unsigned aR[8][4];
#pragma unroll
        for (int k8 = 0; k8 < 8; k8++) {
            aR[k8][0] = sR[(m0 + gq) * P_F + k8 * 8 + tq];
            aR[k8][1] = sR[(m0 + gq + 8) * P_F + k8 * 8 + tq];
            aR[k8][2] = sR[(m0 + gq) * P_F + k8 * 8 + tq + 4];
            aR[k8][3] = sR[(m0 + gq + 8) * P_F + k8 * 8 + tq + 4];
        }
#pragma unroll
        for (int n8 = 0; n8 < 8; n8++) {
#pragma unroll
            for (int k8 = 0; k8 < 8; k8++) {
                unsigned b0 = sW2[(cc + k8 * 8 + tq) * P_W2 + n8 * 8 + gq];
                unsigned b1r = sW2[(cc + k8 * 8 + tq + 4) * P_W2 + n8 * 8 + gq];
                MMA_TF32(o0[n8], o1[n8], o2[n8], o3[n8],
                         aR[k8][0], aR[k8][1], aR[k8][2], aR[k8][3], b0, b1r);
            }
        }
        __syncwarp();
    }

    // ---- epilogue: + b2, store ----
#pragma unroll
    for (int n8 = 0; n8 < 8; n8++) {
        float bb0 = __ldg(b2 + n8 * 8 + 2 * tq);
        float bb1 = __ldg(b2 + n8 * 8 + 2 * tq + 1);
        int r0i = base + m0 + gq;
        int r1i = r0i + 8;
        if (r0i < B) {
            float2 v = make_float2(o0[n8] + bb0, o1[n8] + bb1);
            *(float2*)(out + (size_t)r0i * 64 + n8 * 8 + 2 * tq) = v;
        }
        if (r1i < B) {
            float2 v = make_float2(o2[n8] + bb0, o3[n8] + bb1);
            *(float2*)(out + (size_t)r1i * 64 + n8 * 8 + 2 * tq) = v;
        }
    }
}

// ---------------------------------------------------------------------------
extern "C" void kernel_launch(void* const* d_in, const int* in_sizes, int n_in,
                              void* d_out, int out_size) {
    const float* rp0      = (const float*)d_in[0];
    const float* rp1      = (const float*)d_in[1];
    const float* rp2      = (const float*)d_in[2];
    const float* rp3      = (const float*)d_in[3];
    const float* times    = (const float*)d_in[4];
    const float* now_time = (const float*)d_in[5];
    const float* w1       = (const float*)d_in[6];
    const float* b1       = (const float*)d_in[7];
    const float* w2       = (const float*)d_in[8];
    const float* b2       = (const float*)d_in[9];
    const int*   src      = (const int*)d_in[10];
    const int*   dst      = (const int*)d_in[11];
    const int*   qs       = (const int*)d_in[12];
    const int*   qd       = (const int*)d_in[13];

    int E = in_sizes[4];
    int B = in_sizes[12];
    int N = in_sizes[1] / DD;

    cudaFuncSetAttribute(k_mlp, cudaFuncAttributeMaxDynamicSharedMemorySize,
                         SMEM_MLP * 4);

    k_scalars<<<1, 1>>>(times, now_time, E);
    k_zero<<<(N + 255) / 256, 256>>>(N);
    k_build<<<(E + 255) / 256, 256>>>(src, dst, times, E);
    k_pair<<<B, 64>>>(rp0, rp1, rp2, rp3, qs, qd, B);
    k_mlp<<<(B + 127) / 128, 256, SMEM_MLP * 4>>>(w1, b1, w2, b2,
                                                  (float*)d_out, B);
}